// round 1
// baseline (speedup 1.0000x reference)
#include <cuda_runtime.h>
#include <math.h>

// Problem constants
#define Bn 64
#define Cn 60
#define Tn 4096
#define Jn 270
#define MMn 1024   // K*K = 32*32

// ---------------- device scratch (no allocs allowed) ----------------
__device__ float g_cs[Cn * MMn];        // cos table [c][m]
__device__ float g_sn[Cn * MMn];        // sin table [c][m]
__device__ float g_apart[8 * 288 * 64]; // logit partials [ms][j(288)][c(64)]
__device__ float g_w[Jn * Cn];          // softmax weights [j][c]

// ---------------- f32x2 packed FMA helpers (sm_103a) ----------------
typedef unsigned long long ull;
__device__ __forceinline__ ull pack2(float lo, float hi) {
    ull r; asm("mov.b64 %0, {%1, %2};" : "=l"(r) : "f"(lo), "f"(hi)); return r;
}
__device__ __forceinline__ ull fma2(ull a, ull b, ull c) {
    ull d; asm("fma.rn.f32x2 %0, %1, %2, %3;" : "=l"(d) : "l"(a), "l"(b), "l"(c)); return d;
}
__device__ __forceinline__ void unpack2(ull v, float& lo, float& hi) {
    asm("mov.b64 {%0, %1}, %2;" : "=f"(lo), "=f"(hi) : "l"(v));
}

// ---------------- Kernel A: trig tables ----------------
// g_cs[c][m] = cos(2*pi*(k*x_c + l*y_c)), m = k*32 + l
__global__ void k_tables(const float* __restrict__ loc) {
    int c = blockIdx.x;
    float x = loc[c * 2 + 0];
    float y = loc[c * 2 + 1];
    const double TWO_PI = 6.283185307179586476925286766559;
    for (int m = threadIdx.x; m < MMn; m += blockDim.x) {
        int k = m >> 5, l = m & 31;
        double ph = TWO_PI * ((double)k * (double)x + (double)l * (double)y);
        double s, cv;
        sincos(ph, &s, &cv);
        g_cs[c * MMn + m] = (float)cv;
        g_sn[c * MMn + m] = (float)s;
    }
}

// ---------------- Kernel B: logits GEMM (partials over m-splits) ----------------
// a[j][c] = sum_m z_re[j][m]*cs[c][m] + z_im[j][m]*sn[c][m]
// grid (9 jtiles, 2 ctiles, 8 msplits), block 256 = 16x16, thread tile 2x2
__global__ __launch_bounds__(256) void k_logits(const float* __restrict__ z_re,
                                                const float* __restrict__ z_im) {
    __shared__ float zr[32][65], zi[32][65], tc[32][65], ts[32][65];
    int j0 = blockIdx.x * 32;
    int c0 = blockIdx.y * 32;
    int m0 = blockIdx.z * 128;
    int tid = threadIdx.x;
    int tx = tid & 15, ty = tid >> 4;

    float a00 = 0.f, a01 = 0.f, a10 = 0.f, a11 = 0.f;

    for (int mc = 0; mc < 128; mc += 64) {
        __syncthreads();
        // cooperative load: 32 rows x 64 m for each of 4 arrays
        for (int i = tid; i < 2048; i += 256) {
            int rr = i >> 6, mm = i & 63;
            int gm = m0 + mc + mm;
            int j = j0 + rr;
            float vr = 0.f, vi = 0.f;
            if (j < Jn) { vr = z_re[j * MMn + gm]; vi = z_im[j * MMn + gm]; }
            zr[rr][mm] = vr; zi[rr][mm] = vi;
            int c = c0 + rr;
            float vc = 0.f, vs = 0.f;
            if (c < Cn) { vc = g_cs[c * MMn + gm]; vs = g_sn[c * MMn + gm]; }
            tc[rr][mm] = vc; ts[rr][mm] = vs;
        }
        __syncthreads();
        #pragma unroll 16
        for (int mm = 0; mm < 64; mm++) {
            float r0 = zr[ty][mm],      r1 = zr[ty + 16][mm];
            float i0 = zi[ty][mm],      i1 = zi[ty + 16][mm];
            float c0v = tc[tx][mm],     c1v = tc[tx + 16][mm];
            float s0v = ts[tx][mm],     s1v = ts[tx + 16][mm];
            a00 += r0 * c0v + i0 * s0v;
            a01 += r0 * c1v + i0 * s1v;
            a10 += r1 * c0v + i1 * s0v;
            a11 += r1 * c1v + i1 * s1v;
        }
    }
    int ms = blockIdx.z;
    g_apart[(ms * 288 + j0 + ty)      * 64 + c0 + tx]      = a00;
    g_apart[(ms * 288 + j0 + ty)      * 64 + c0 + tx + 16] = a01;
    g_apart[(ms * 288 + j0 + ty + 16) * 64 + c0 + tx]      = a10;
    g_apart[(ms * 288 + j0 + ty + 16) * 64 + c0 + tx + 16] = a11;
}

// ---------------- Kernel C: softmax over c per row j ----------------
__global__ void k_softmax() {
    int j = blockIdx.x;
    int lane = threadIdx.x;  // 0..31
    float a1 = 0.f, a2 = 0.f;
    #pragma unroll
    for (int ms = 0; ms < 8; ms++) {
        a1 += g_apart[(ms * 288 + j) * 64 + lane];
        if (lane + 32 < Cn) a2 += g_apart[(ms * 288 + j) * 64 + lane + 32];
    }
    float e1 = expf(a1);
    float e2 = (lane + 32 < Cn) ? expf(a2) : 0.f;
    float s = e1 + e2;
    #pragma unroll
    for (int o = 16; o > 0; o >>= 1) s += __shfl_xor_sync(0xffffffffu, s, o);
    g_w[j * Cn + lane] = e1 / s;
    if (lane + 32 < Cn) g_w[j * Cn + lane + 32] = e2 / s;
}

// ---------------- Kernel D: main GEMM  Y[b][j][t] = sum_c w[j][c] X[b][c][t] ----------------
// grid (32 t-tiles, 64 b), block 288 = 32 t-lanes x 9 j-lanes; thread: 6 j x 4 t
__global__ __launch_bounds__(288) void k_out(const float* __restrict__ X,
                                             float* __restrict__ Y) {
    __shared__ __align__(16) float xs[Cn * 128];   // [c][128 t]
    __shared__ float ws[54 * 60];                   // [jj][c] for current chunk

    int b  = blockIdx.y;
    int t0 = blockIdx.x * 128;
    int tid = threadIdx.x;

    // load X tile (60 x 128 floats) as float4
    const float4* X4 = (const float4*)(X + (size_t)b * Cn * Tn + t0);
    float4* xs4 = (float4*)xs;
    for (int i = tid; i < Cn * 32; i += 288) {
        int row = i >> 5, col = i & 31;
        xs4[i] = X4[row * (Tn / 4) + col];
    }

    int tx = tid & 31;      // t lane (4 floats)
    int jy = tid >> 5;      // 0..8

    for (int ch = 0; ch < 5; ch++) {
        __syncthreads();   // xs ready (first iter) / prev ws reads done
        for (int i = tid; i < 54 * 60; i += 288) ws[i] = g_w[ch * 54 * 60 + i];
        __syncthreads();

        ull accA[6], accB[6];
        #pragma unroll
        for (int r = 0; r < 6; r++) { accA[r] = pack2(0.f, 0.f); accB[r] = accA[r]; }

        #pragma unroll 4
        for (int c = 0; c < Cn; c++) {
            float4 x4 = xs4[c * 32 + tx];
            ull xa = pack2(x4.x, x4.y);
            ull xb = pack2(x4.z, x4.w);
            #pragma unroll
            for (int r = 0; r < 6; r++) {
                float wv = ws[(jy * 6 + r) * 60 + c];   // warp-uniform -> LDS broadcast
                ull wp = pack2(wv, wv);
                accA[r] = fma2(wp, xa, accA[r]);
                accB[r] = fma2(wp, xb, accB[r]);
            }
        }

        #pragma unroll
        for (int r = 0; r < 6; r++) {
            int j = ch * 54 + jy * 6 + r;   // exact: 5*54 = 270
            float4 o;
            unpack2(accA[r], o.x, o.y);
            unpack2(accB[r], o.z, o.w);
            ((float4*)(Y + ((size_t)b * Jn + j) * Tn + t0))[tx] = o;
        }
    }
}

// ---------------- launch ----------------
extern "C" void kernel_launch(void* const* d_in, const int* in_sizes, int n_in,
                              void* d_out, int out_size) {
    // Defensive input identification by element count (metadata order: X, z_re, z_im, loc)
    const float* X = nullptr; const float* z_re = nullptr;
    const float* z_im = nullptr; const float* loc = nullptr;
    for (int i = 0; i < n_in; i++) {
        int s = in_sizes[i];
        if (s == Bn * Cn * Tn)      X = (const float*)d_in[i];
        else if (s == Cn * 2)       loc = (const float*)d_in[i];
        else if (s == Jn * MMn) {   // z_re first, z_im second in metadata order
            if (!z_re) z_re = (const float*)d_in[i];
            else       z_im = (const float*)d_in[i];
        }
    }
    float* Y = (float*)d_out;

    k_tables<<<Cn, 256>>>(loc);
    k_logits<<<dim3(9, 2, 8), 256>>>(z_re, z_im);
    k_softmax<<<Jn, 32>>>();
    k_out<<<dim3(Tn / 128, Bn), 288>>>(X, Y);
}

// round 7
// speedup vs baseline: 1.0167x; 1.0167x over previous
#include <cuda_runtime.h>
#include <math.h>
#include <stdint.h>

// Problem constants
#define Bn 64
#define Cn 60
#define Tn 4096
#define Jn 270
#define MMn 1024   // K*K = 32*32

// ---------------- device scratch ----------------
__device__ float g_cs[Cn * MMn];        // cos table [c][m]
__device__ float g_sn[Cn * MMn];        // sin table [c][m]
__device__ float g_apart[8 * 288 * 64]; // logit partials [ms][j(288)][c(64)]
__device__ float g_w[Jn * Cn];          // softmax weights [j][c]

__device__ __forceinline__ float tf32_rna(float v) {
    float r; asm("cvt.rna.tf32.f32 %0, %1;" : "=f"(r) : "f"(v)); return r;
}

// m16n8k8 tf32 mma: D += A(row,16x8) * B(col,8x8)
__device__ __forceinline__ void mma8(float* d, const uint32_t* a, const uint32_t* b) {
    asm volatile(
        "mma.sync.aligned.m16n8k8.row.col.f32.tf32.tf32.f32 "
        "{%0,%1,%2,%3}, {%4,%5,%6,%7}, {%8,%9}, {%0,%1,%2,%3};"
        : "+f"(d[0]), "+f"(d[1]), "+f"(d[2]), "+f"(d[3])
        : "r"(a[0]), "r"(a[1]), "r"(a[2]), "r"(a[3]), "r"(b[0]), "r"(b[1]));
}

// ---------------- Kernel A: trig tables ----------------
__global__ void k_tables(const float* __restrict__ loc) {
    int c = blockIdx.x;
    float x = loc[c * 2 + 0];
    float y = loc[c * 2 + 1];
    for (int m = threadIdx.x; m < MMn; m += blockDim.x) {
        int k = m >> 5, l = m & 31;
        double r = (double)k * (double)x + (double)l * (double)y;  // exact in double
        r -= rint(r);                                              // frac in [-0.5, 0.5]
        float fr = (float)r;
        float s, cv;
        sincospif(2.0f * fr, &s, &cv);   // == sin/cos(2*pi*(kx+ly))
        g_cs[c * MMn + m] = cv;
        g_sn[c * MMn + m] = s;
    }
}

// ---------------- Kernel B: logits GEMM ----------------
__global__ __launch_bounds__(256) void k_logits(const float* __restrict__ z_re,
                                                const float* __restrict__ z_im) {
    __shared__ float zr[32][65], zi[32][65], tc[32][65], ts[32][65];
    int j0 = blockIdx.x * 32;
    int c0 = blockIdx.y * 32;
    int m0 = blockIdx.z * 128;
    int tid = threadIdx.x;
    int tx = tid & 15, ty = tid >> 4;

    float a00 = 0.f, a01 = 0.f, a10 = 0.f, a11 = 0.f;

    for (int mc = 0; mc < 128; mc += 64) {
        __syncthreads();
        for (int i = tid; i < 2048; i += 256) {
            int rr = i >> 6, mm = i & 63;
            int gm = m0 + mc + mm;
            int j = j0 + rr;
            float vr = 0.f, vi = 0.f;
            if (j < Jn) { vr = z_re[j * MMn + gm]; vi = z_im[j * MMn + gm]; }
            zr[rr][mm] = vr; zi[rr][mm] = vi;
            int c = c0 + rr;
            float vc = 0.f, vs = 0.f;
            if (c < Cn) { vc = g_cs[c * MMn + gm]; vs = g_sn[c * MMn + gm]; }
            tc[rr][mm] = vc; ts[rr][mm] = vs;
        }
        __syncthreads();
        #pragma unroll 16
        for (int mm = 0; mm < 64; mm++) {
            float r0 = zr[ty][mm],      r1 = zr[ty + 16][mm];
            float i0 = zi[ty][mm],      i1 = zi[ty + 16][mm];
            float c0v = tc[tx][mm],     c1v = tc[tx + 16][mm];
            float s0v = ts[tx][mm],     s1v = ts[tx + 16][mm];
            a00 += r0 * c0v + i0 * s0v;
            a01 += r0 * c1v + i0 * s1v;
            a10 += r1 * c0v + i1 * s0v;
            a11 += r1 * c1v + i1 * s1v;
        }
    }
    int ms = blockIdx.z;
    g_apart[(ms * 288 + j0 + ty)      * 64 + c0 + tx]      = a00;
    g_apart[(ms * 288 + j0 + ty)      * 64 + c0 + tx + 16] = a01;
    g_apart[(ms * 288 + j0 + ty + 16) * 64 + c0 + tx]      = a10;
    g_apart[(ms * 288 + j0 + ty + 16) * 64 + c0 + tx + 16] = a11;
}

// ---------------- Kernel C: softmax over c per row j ----------------
__global__ void k_softmax() {
    int j = blockIdx.x;
    int lane = threadIdx.x;
    float a1 = 0.f, a2 = 0.f;
    #pragma unroll
    for (int ms = 0; ms < 8; ms++) {
        a1 += g_apart[(ms * 288 + j) * 64 + lane];
        if (lane + 32 < Cn) a2 += g_apart[(ms * 288 + j) * 64 + lane + 32];
    }
    float e1 = expf(a1);
    float e2 = (lane + 32 < Cn) ? expf(a2) : 0.f;
    float s = e1 + e2;
    #pragma unroll
    for (int o = 16; o > 0; o >>= 1) s += __shfl_xor_sync(0xffffffffu, s, o);
    g_w[j * Cn + lane] = e1 / s;
    if (lane + 32 < Cn) g_w[j * Cn + lane + 32] = e2 / s;
}

// ---------------- Kernel D: main GEMM via mma.sync tf32 ----------------
// D[j, t] = sum_c w[j,c] * X[b,c,t].   A = w (row-major, M=j), B = X (col-major K x N = c x t).
// CTA: 96 j x 128 t x 64 k. 256 threads = 8 warps (2 j-halves x 4 t-quarters).
// Warp: 48 j x 32 t = 3 m-tiles x 4 n-tiles. X split hi+lo tf32; w rounded to tf32.
#define JT 96
#define WS_STRIDE 68    // floats; A-frag banks = 4*gid+tig -> conflict-free
#define XS_STRIDE 136   // floats; B-frag banks = 8*tig+gid -> conflict-free
#define WS_OFF 0u                                  // 96*68*4   = 26112 B
#define XH_OFF 26112u                              // 64*136*4  = 34816 B
#define XL_OFF (26112u + 34816u)
#define SM_TOTAL (26112u + 2u * 34816u)            // 95744 B

__global__ __launch_bounds__(256) void k_main(const float* __restrict__ X,
                                              float* __restrict__ Y) {
    extern __shared__ __align__(16) char smem[];
    float* ws = (float*)(smem + WS_OFF);
    float* xh = (float*)(smem + XH_OFF);
    float* xl = (float*)(smem + XL_OFF);

    const int tid  = threadIdx.x;
    const int lane = tid & 31;
    const int warp = tid >> 5;
    const int gid  = lane >> 2;    // 0..7
    const int tig  = lane & 3;     // 0..3
    const int mw   = warp & 1;     // j half (48)
    const int nw   = warp >> 1;    // t quarter (32)

    const int jt = blockIdx.x;           // 0..2
    const int t0 = blockIdx.y * 128;
    const int b  = blockIdx.z;
    const int j0 = jt * JT;

    // --- load w tile -> ws (tf32-rounded), zero-padded ---
    for (int q = tid; q < JT * 64; q += 256) {
        int jj = q >> 6, c = q & 63;
        int j = j0 + jj;
        float v = (j < Jn && c < Cn) ? g_w[j * Cn + c] : 0.f;
        ws[jj * WS_STRIDE + c] = tf32_rna(v);
    }

    // --- load X tile -> xh/xl (hi + lo tf32 split), coalesced float4 ---
    const float4* X4 = (const float4*)(X + (size_t)b * Cn * Tn + t0);
    for (int q = tid; q < Cn * 32; q += 256) {
        int c = q >> 5, t4 = q & 31;
        float4 v = X4[(size_t)c * (Tn / 4) + t4];
        float4 hi, lo;
        hi.x = tf32_rna(v.x); lo.x = tf32_rna(v.x - hi.x);
        hi.y = tf32_rna(v.y); lo.y = tf32_rna(v.y - hi.y);
        hi.z = tf32_rna(v.z); lo.z = tf32_rna(v.z - hi.z);
        hi.w = tf32_rna(v.w); lo.w = tf32_rna(v.w - hi.w);
        *(float4*)&xh[c * XS_STRIDE + t4 * 4] = hi;
        *(float4*)&xl[c * XS_STRIDE + t4 * 4] = lo;
    }
    // zero-pad k rows 60..63
    for (int q = tid; q < 4 * 32; q += 256) {
        int c = Cn + (q >> 5), t4 = q & 31;
        float4 z = make_float4(0.f, 0.f, 0.f, 0.f);
        *(float4*)&xh[c * XS_STRIDE + t4 * 4] = z;
        *(float4*)&xl[c * XS_STRIDE + t4 * 4] = z;
    }
    __syncthreads();

    float acc[3][4][4];
    #pragma unroll
    for (int mt = 0; mt < 3; mt++)
        #pragma unroll
        for (int nt = 0; nt < 4; nt++)
            #pragma unroll
            for (int r = 0; r < 4; r++) acc[mt][nt][r] = 0.f;

    const uint32_t* wsb = (const uint32_t*)ws;
    const uint32_t* xhb = (const uint32_t*)xh;
    const uint32_t* xlb = (const uint32_t*)xl;

    #pragma unroll
    for (int k0 = 0; k0 < 64; k0 += 8) {
        uint32_t a[3][4];
        #pragma unroll
        for (int mt = 0; mt < 3; mt++) {
            int jm = mw * 48 + mt * 16;
            a[mt][0] = wsb[(jm + gid)     * WS_STRIDE + k0 + tig];
            a[mt][1] = wsb[(jm + gid + 8) * WS_STRIDE + k0 + tig];
            a[mt][2] = wsb[(jm + gid)     * WS_STRIDE + k0 + tig + 4];
            a[mt][3] = wsb[(jm + gid + 8) * WS_STRIDE + k0 + tig + 4];
        }
        uint32_t bh[4][2], bl[4][2];
        #pragma unroll
        for (int nt = 0; nt < 4; nt++) {
            int tcol = nw * 32 + nt * 8 + gid;
            bh[nt][0] = xhb[(k0 + tig)     * XS_STRIDE + tcol];
            bh[nt][1] = xhb[(k0 + tig + 4) * XS_STRIDE + tcol];
            bl[nt][0] = xlb[(k0 + tig)     * XS_STRIDE + tcol];
            bl[nt][1] = xlb[(k0 + tig + 4) * XS_STRIDE + tcol];
        }
        #pragma unroll
        for (int mt = 0; mt < 3; mt++)
            #pragma unroll
            for (int nt = 0; nt < 4; nt++) {
                mma8(acc[mt][nt], a[mt], bh[nt]);
                mma8(acc[mt][nt], a[mt], bl[nt]);
            }
    }

    // --- store: float2 per (reg pair), j-bound predicated ---
    #pragma unroll
    for (int mt = 0; mt < 3; mt++) {
        int j = j0 + mw * 48 + mt * 16 + gid;
        #pragma unroll
        for (int nt = 0; nt < 4; nt++) {
            int t = t0 + nw * 32 + nt * 8 + tig * 2;
            float* base = Y + ((size_t)b * Jn + j) * Tn + t;
            if (j < Jn)
                *(float2*)base = make_float2(acc[mt][nt][0], acc[mt][nt][1]);
            if (j + 8 < Jn)
                *(float2*)(base + 8 * (size_t)Tn) = make_float2(acc[mt][nt][2], acc[mt][nt][3]);
        }
    }
}

// ---------------- launch ----------------
extern "C" void kernel_launch(void* const* d_in, const int* in_sizes, int n_in,
                              void* d_out, int out_size) {
    const float* X = nullptr; const float* z_re = nullptr;
    const float* z_im = nullptr; const float* loc = nullptr;
    for (int i = 0; i < n_in; i++) {
        int s = in_sizes[i];
        if (s == Bn * Cn * Tn)      X = (const float*)d_in[i];
        else if (s == Cn * 2)       loc = (const float*)d_in[i];
        else if (s == Jn * MMn) {
            if (!z_re) z_re = (const float*)d_in[i];
            else       z_im = (const float*)d_in[i];
        }
    }
    float* Y = (float*)d_out;

    (void)cudaFuncSetAttribute(k_main, cudaFuncAttributeMaxDynamicSharedMemorySize, SM_TOTAL);

    k_tables<<<Cn, 256>>>(loc);
    k_logits<<<dim3(9, 2, 8), 256>>>(z_re, z_im);
    k_softmax<<<Jn, 32>>>();
    k_main<<<dim3(3, Tn / 128, Bn), 256, SM_TOTAL>>>(X, Y);
}

// round 9
// speedup vs baseline: 1.4368x; 1.4133x over previous
#include <cuda_runtime.h>
#include <math.h>
#include <stdint.h>

// Problem constants
#define Bn 64
#define Cn 60
#define Tn 4096
#define Jn 270
#define MMn 1024   // K*K = 32*32

// ---------------- device scratch ----------------
__device__ float g_cs[Cn * MMn];        // cos table [c][m]
__device__ float g_sn[Cn * MMn];        // sin table [c][m]
__device__ float g_apart[8 * 288 * 64]; // logit partials [ms][j(288)][c(64)]
__device__ float g_w[Jn * Cn];          // softmax weights [j][c]

__device__ __forceinline__ float tf32_rna(float v) {
    float r; asm("cvt.rna.tf32.f32 %0, %1;" : "=f"(r) : "f"(v)); return r;
}

// m16n8k8 tf32 mma: D += A(row,16x8) * B(col,8x8)
__device__ __forceinline__ void mma8(float* d, const uint32_t* a, const uint32_t* b) {
    asm volatile(
        "mma.sync.aligned.m16n8k8.row.col.f32.tf32.tf32.f32 "
        "{%0,%1,%2,%3}, {%4,%5,%6,%7}, {%8,%9}, {%0,%1,%2,%3};"
        : "+f"(d[0]), "+f"(d[1]), "+f"(d[2]), "+f"(d[3])
        : "r"(a[0]), "r"(a[1]), "r"(a[2]), "r"(a[3]), "r"(b[0]), "r"(b[1]));
}

// ---------------- Kernel A: trig tables ----------------
__global__ void k_tables(const float* __restrict__ loc) {
    int c = blockIdx.x;
    float x = loc[c * 2 + 0];
    float y = loc[c * 2 + 1];
    for (int m = threadIdx.x; m < MMn; m += blockDim.x) {
        int k = m >> 5, l = m & 31;
        float r = (float)k * x + (float)l * y;   // |err| <~ 4e-6 of a period
        r -= rintf(r);                           // frac in [-0.5, 0.5]
        float s, cv;
        sincospif(2.0f * r, &s, &cv);            // == sin/cos(2*pi*(kx+ly))
        g_cs[c * MMn + m] = cv;
        g_sn[c * MMn + m] = s;
    }
}

// ---------------- Kernel B: logits GEMM ----------------
__global__ __launch_bounds__(256) void k_logits(const float* __restrict__ z_re,
                                                const float* __restrict__ z_im) {
    __shared__ float zr[32][65], zi[32][65], tc[32][65], ts[32][65];
    int j0 = blockIdx.x * 32;
    int c0 = blockIdx.y * 32;
    int m0 = blockIdx.z * 128;
    int tid = threadIdx.x;
    int tx = tid & 15, ty = tid >> 4;

    float a00 = 0.f, a01 = 0.f, a10 = 0.f, a11 = 0.f;

    for (int mc = 0; mc < 128; mc += 64) {
        __syncthreads();
        for (int i = tid; i < 2048; i += 256) {
            int rr = i >> 6, mm = i & 63;
            int gm = m0 + mc + mm;
            int j = j0 + rr;
            float vr = 0.f, vi = 0.f;
            if (j < Jn) { vr = z_re[j * MMn + gm]; vi = z_im[j * MMn + gm]; }
            zr[rr][mm] = vr; zi[rr][mm] = vi;
            int c = c0 + rr;
            float vc = 0.f, vs = 0.f;
            if (c < Cn) { vc = g_cs[c * MMn + gm]; vs = g_sn[c * MMn + gm]; }
            tc[rr][mm] = vc; ts[rr][mm] = vs;
        }
        __syncthreads();
        #pragma unroll 16
        for (int mm = 0; mm < 64; mm++) {
            float r0 = zr[ty][mm],      r1 = zr[ty + 16][mm];
            float i0 = zi[ty][mm],      i1 = zi[ty + 16][mm];
            float c0v = tc[tx][mm],     c1v = tc[tx + 16][mm];
            float s0v = ts[tx][mm],     s1v = ts[tx + 16][mm];
            a00 += r0 * c0v + i0 * s0v;
            a01 += r0 * c1v + i0 * s1v;
            a10 += r1 * c0v + i1 * s0v;
            a11 += r1 * c1v + i1 * s1v;
        }
    }
    int ms = blockIdx.z;
    g_apart[(ms * 288 + j0 + ty)      * 64 + c0 + tx]      = a00;
    g_apart[(ms * 288 + j0 + ty)      * 64 + c0 + tx + 16] = a01;
    g_apart[(ms * 288 + j0 + ty + 16) * 64 + c0 + tx]      = a10;
    g_apart[(ms * 288 + j0 + ty + 16) * 64 + c0 + tx + 16] = a11;
}

// ---------------- Kernel C: softmax over c per row j ----------------
__global__ void k_softmax() {
    int j = blockIdx.x;
    int lane = threadIdx.x;
    float a1 = 0.f, a2 = 0.f;
    #pragma unroll
    for (int ms = 0; ms < 8; ms++) {
        a1 += g_apart[(ms * 288 + j) * 64 + lane];
        if (lane + 32 < Cn) a2 += g_apart[(ms * 288 + j) * 64 + lane + 32];
    }
    float e1 = expf(a1);
    float e2 = (lane + 32 < Cn) ? expf(a2) : 0.f;
    float s = e1 + e2;
    #pragma unroll
    for (int o = 16; o > 0; o >>= 1) s += __shfl_xor_sync(0xffffffffu, s, o);
    g_w[j * Cn + lane] = e1 / s;
    if (lane + 32 < Cn) g_w[j * Cn + lane + 32] = e2 / s;
}

// ---------------- Kernel D: main GEMM via mma.sync tf32 ----------------
// D[j, t] = sum_c w[j,c] * X[b,c,t].   A = w (row, M=j), B = X (col, K x N = c x t).
// CTA: 96 j x 128 t x 64 k. 256 threads = 8 warps (2 j-halves x 4 t-quarters).
// Warp: 48 j x 32 t = 3 m-tiles x 4 n-tiles. Single tf32 (rna) on both operands.
#define JT 96
#define WS_STRIDE 68    // floats; A-frag banks = 4*gid+tig -> conflict-free
#define XS_STRIDE 136   // floats; B-frag banks = 8*tig+gid -> conflict-free
#define WS_OFF 0u                        // 96*68*4  = 26112 B
#define XS_OFF 26112u                    // 64*136*4 = 34816 B
#define SM_TOTAL (26112u + 34816u)       // 60928 B -> 3 CTAs/SM

__global__ __launch_bounds__(256, 3) void k_main_v3(const float* __restrict__ X,
                                                    float* __restrict__ Y) {
    extern __shared__ __align__(16) char smem[];
    float* ws = (float*)(smem + WS_OFF);
    float* xs = (float*)(smem + XS_OFF);

    const int tid  = threadIdx.x;
    const int lane = tid & 31;
    const int warp = tid >> 5;
    const int gid  = lane >> 2;    // 0..7
    const int tig  = lane & 3;     // 0..3
    const int mw   = warp & 1;     // j half (48)
    const int nw   = warp >> 1;    // t quarter (32)

    const int jt = blockIdx.x;           // 0..2 (fastest -> L2 reuse of X tile)
    const int t0 = blockIdx.y * 128;
    const int b  = blockIdx.z;
    const int j0 = jt * JT;

    // --- load w tile -> ws (tf32-rounded), zero-padded ---
    for (int q = tid; q < JT * 64; q += 256) {
        int jj = q >> 6, c = q & 63;
        int j = j0 + jj;
        float v = (j < Jn && c < Cn) ? g_w[j * Cn + c] : 0.f;
        ws[jj * WS_STRIDE + c] = tf32_rna(v);
    }

    // --- load X tile -> xs (tf32-rounded), coalesced float4 ---
    const float4* X4 = (const float4*)(X + (size_t)b * Cn * Tn + t0);
    for (int q = tid; q < Cn * 32; q += 256) {
        int c = q >> 5, t4 = q & 31;
        float4 v = X4[(size_t)c * (Tn / 4) + t4];
        v.x = tf32_rna(v.x);
        v.y = tf32_rna(v.y);
        v.z = tf32_rna(v.z);
        v.w = tf32_rna(v.w);
        *(float4*)&xs[c * XS_STRIDE + t4 * 4] = v;
    }
    // zero-pad k rows 60..63
    for (int q = tid; q < 4 * 32; q += 256) {
        int c = Cn + (q >> 5), t4 = q & 31;
        *(float4*)&xs[c * XS_STRIDE + t4 * 4] = make_float4(0.f, 0.f, 0.f, 0.f);
    }
    __syncthreads();

    float acc[3][4][4] = {};

    const uint32_t* wsb = (const uint32_t*)ws;
    const uint32_t* xsb = (const uint32_t*)xs;

    #pragma unroll
    for (int k0 = 0; k0 < 64; k0 += 8) {
        uint32_t a[3][4];
        #pragma unroll
        for (int mt = 0; mt < 3; mt++) {
            int jm = mw * 48 + mt * 16;
            a[mt][0] = wsb[(jm + gid)     * WS_STRIDE + k0 + tig];
            a[mt][1] = wsb[(jm + gid + 8) * WS_STRIDE + k0 + tig];
            a[mt][2] = wsb[(jm + gid)     * WS_STRIDE + k0 + tig + 4];
            a[mt][3] = wsb[(jm + gid + 8) * WS_STRIDE + k0 + tig + 4];
        }
        uint32_t bv[4][2];
        #pragma unroll
        for (int nt = 0; nt < 4; nt++) {
            int tcol = nw * 32 + nt * 8 + gid;
            bv[nt][0] = xsb[(k0 + tig)     * XS_STRIDE + tcol];
            bv[nt][1] = xsb[(k0 + tig + 4) * XS_STRIDE + tcol];
        }
        #pragma unroll
        for (int mt = 0; mt < 3; mt++)
            #pragma unroll
            for (int nt = 0; nt < 4; nt++)
                mma8(acc[mt][nt], a[mt], bv[nt]);
    }

    // --- store: float2 per reg pair, j-bound predicated ---
    #pragma unroll
    for (int mt = 0; mt < 3; mt++) {
        int j = j0 + mw * 48 + mt * 16 + gid;
        #pragma unroll
        for (int nt = 0; nt < 4; nt++) {
            int t = t0 + nw * 32 + nt * 8 + tig * 2;
            float* base = Y + ((size_t)b * Jn + j) * Tn + t;
            if (j < Jn)
                *(float2*)base = make_float2(acc[mt][nt][0], acc[mt][nt][1]);
            if (j + 8 < Jn)
                *(float2*)(base + 8 * (size_t)Tn) = make_float2(acc[mt][nt][2], acc[mt][nt][3]);
        }
    }
}

// ---------------- launch ----------------
extern "C" void kernel_launch(void* const* d_in, const int* in_sizes, int n_in,
                              void* d_out, int out_size) {
    const float* X = nullptr; const float* z_re = nullptr;
    const float* z_im = nullptr; const float* loc = nullptr;
    for (int i = 0; i < n_in; i++) {
        int s = in_sizes[i];
        if (s == Bn * Cn * Tn)      X = (const float*)d_in[i];
        else if (s == Cn * 2)       loc = (const float*)d_in[i];
        else if (s == Jn * MMn) {
            if (!z_re) z_re = (const float*)d_in[i];
            else       z_im = (const float*)d_in[i];
        }
    }
    float* Y = (float*)d_out;

    (void)cudaFuncSetAttribute(k_main_v3, cudaFuncAttributeMaxDynamicSharedMemorySize, SM_TOTAL);

    k_tables<<<Cn, 256>>>(loc);
    k_logits<<<dim3(9, 2, 8), 256>>>(z_re, z_im);
    k_softmax<<<Jn, 32>>>();
    k_main_v3<<<dim3(3, Tn / 128, Bn), 256, SM_TOTAL>>>(X, Y);
}

// round 10
// speedup vs baseline: 2.0422x; 1.4213x over previous
#include <cuda_runtime.h>
#include <math.h>
#include <stdint.h>

// Problem constants
#define Bn 64
#define Cn 60
#define Tn 4096
#define Jn 270
#define MMn 1024   // K*K = 32*32

// ---------------- device scratch ----------------
__device__ float g_cs[Cn * MMn];        // cos table [c][m]
__device__ float g_sn[Cn * MMn];        // sin table [c][m]
__device__ float g_apart[8 * 288 * 64]; // logit partials [ms][j(288)][c(64)]
__device__ float g_w[Jn * Cn];          // softmax weights [j][c]

__device__ __forceinline__ float tf32_rna(float v) {
    float r; asm("cvt.rna.tf32.f32 %0, %1;" : "=f"(r) : "f"(v)); return r;
}
__device__ __forceinline__ uint32_t smem_u32(const void* p) {
    uint32_t a;
    asm("{ .reg .u64 t; cvta.to.shared.u64 t, %1; cvt.u32.u64 %0, t; }" : "=r"(a) : "l"(p));
    return a;
}
__device__ __forceinline__ void cp16(uint32_t dst, const void* src) {
    asm volatile("cp.async.cg.shared.global [%0], [%1], 16;" :: "r"(dst), "l"(src));
}
#define CP_COMMIT() asm volatile("cp.async.commit_group;" ::: "memory")
#define CP_WAIT(n)  asm volatile("cp.async.wait_group %0;" :: "n"(n) : "memory")

// m16n8k8 tf32 mma: D += A(row,16x8) * B(col,8x8)
__device__ __forceinline__ void mma8(float* d, const uint32_t* a, const uint32_t* b) {
    asm volatile(
        "mma.sync.aligned.m16n8k8.row.col.f32.tf32.tf32.f32 "
        "{%0,%1,%2,%3}, {%4,%5,%6,%7}, {%8,%9}, {%0,%1,%2,%3};"
        : "+f"(d[0]), "+f"(d[1]), "+f"(d[2]), "+f"(d[3])
        : "r"(a[0]), "r"(a[1]), "r"(a[2]), "r"(a[3]), "r"(b[0]), "r"(b[1]));
}

// ---------------- Kernel A: trig tables ----------------
__global__ void k_tables(const float* __restrict__ loc) {
    int c = blockIdx.x;
    float x = loc[c * 2 + 0];
    float y = loc[c * 2 + 1];
    for (int m = threadIdx.x; m < MMn; m += blockDim.x) {
        int k = m >> 5, l = m & 31;
        float r = (float)k * x + (float)l * y;
        r -= rintf(r);
        float s, cv;
        sincospif(2.0f * r, &s, &cv);
        g_cs[c * MMn + m] = cv;
        g_sn[c * MMn + m] = s;
    }
}

// ---------------- Kernel B: logits GEMM ----------------
__global__ __launch_bounds__(256) void k_logits(const float* __restrict__ z_re,
                                                const float* __restrict__ z_im) {
    __shared__ float zr[32][65], zi[32][65], tc[32][65], ts[32][65];
    int j0 = blockIdx.x * 32;
    int c0 = blockIdx.y * 32;
    int m0 = blockIdx.z * 128;
    int tid = threadIdx.x;
    int tx = tid & 15, ty = tid >> 4;

    float a00 = 0.f, a01 = 0.f, a10 = 0.f, a11 = 0.f;

    for (int mc = 0; mc < 128; mc += 64) {
        __syncthreads();
        for (int i = tid; i < 2048; i += 256) {
            int rr = i >> 6, mm = i & 63;
            int gm = m0 + mc + mm;
            int j = j0 + rr;
            float vr = 0.f, vi = 0.f;
            if (j < Jn) { vr = z_re[j * MMn + gm]; vi = z_im[j * MMn + gm]; }
            zr[rr][mm] = vr; zi[rr][mm] = vi;
            int c = c0 + rr;
            float vc = 0.f, vs = 0.f;
            if (c < Cn) { vc = g_cs[c * MMn + gm]; vs = g_sn[c * MMn + gm]; }
            tc[rr][mm] = vc; ts[rr][mm] = vs;
        }
        __syncthreads();
        #pragma unroll 16
        for (int mm = 0; mm < 64; mm++) {
            float r0 = zr[ty][mm],      r1 = zr[ty + 16][mm];
            float i0 = zi[ty][mm],      i1 = zi[ty + 16][mm];
            float c0v = tc[tx][mm],     c1v = tc[tx + 16][mm];
            float s0v = ts[tx][mm],     s1v = ts[tx + 16][mm];
            a00 += r0 * c0v + i0 * s0v;
            a01 += r0 * c1v + i0 * s1v;
            a10 += r1 * c0v + i1 * s0v;
            a11 += r1 * c1v + i1 * s1v;
        }
    }
    int ms = blockIdx.z;
    g_apart[(ms * 288 + j0 + ty)      * 64 + c0 + tx]      = a00;
    g_apart[(ms * 288 + j0 + ty)      * 64 + c0 + tx + 16] = a01;
    g_apart[(ms * 288 + j0 + ty + 16) * 64 + c0 + tx]      = a10;
    g_apart[(ms * 288 + j0 + ty + 16) * 64 + c0 + tx + 16] = a11;
}

// ---------------- Kernel C: softmax over c per row j ----------------
__global__ void k_softmax() {
    int j = blockIdx.x;
    int lane = threadIdx.x;
    float a1 = 0.f, a2 = 0.f;
    #pragma unroll
    for (int ms = 0; ms < 8; ms++) {
        a1 += g_apart[(ms * 288 + j) * 64 + lane];
        if (lane + 32 < Cn) a2 += g_apart[(ms * 288 + j) * 64 + lane + 32];
    }
    float e1 = expf(a1);
    float e2 = (lane + 32 < Cn) ? expf(a2) : 0.f;
    float s = e1 + e2;
    #pragma unroll
    for (int o = 16; o > 0; o >>= 1) s += __shfl_xor_sync(0xffffffffu, s, o);
    g_w[j * Cn + lane] = e1 / s;
    if (lane + 32 < Cn) g_w[j * Cn + lane + 32] = e2 / s;
}

// ---------------- Kernel D: pipelined mma.sync tf32 GEMM ----------------
// CTA: 96 j x 512 t (4 chunks of 128), double-buffered cp.async X; w loaded once.
#define JT 96
#define WS_STRIDE 68    // floats; A-frag banks conflict-free
#define XS_STRIDE 136   // floats; B-frag banks conflict-free; row = 544 B (16B-aligned)
#define WS_OFF 0u                        // 96*68*4  = 26112 B
#define XB0_OFF 26112u                   // 64*136*4 = 34816 B
#define XB1_OFF (26112u + 34816u)
#define SM_TOTAL (26112u + 2u * 34816u)  // 95744 B -> 2 CTAs/SM

__global__ __launch_bounds__(256, 2) void k_main_v4(const float* __restrict__ X,
                                                    float* __restrict__ Y) {
    extern __shared__ __align__(16) char smem[];
    float* ws = (float*)(smem + WS_OFF);
    const uint32_t xb_u32[2] = { smem_u32(smem + XB0_OFF), smem_u32(smem + XB1_OFF) };
    const float* xbuf[2] = { (const float*)(smem + XB0_OFF), (const float*)(smem + XB1_OFF) };

    const int tid  = threadIdx.x;
    const int lane = tid & 31;
    const int warp = tid >> 5;
    const int gid  = lane >> 2;    // 0..7
    const int tig  = lane & 3;     // 0..3
    const int mw   = warp & 1;     // j half (48)
    const int nw   = warp >> 1;    // t quarter (32)

    const int jt = blockIdx.x;            // 0..2 fastest -> L2 reuse of X
    const int T0 = blockIdx.y * 512;      // CTA t origin
    const int b  = blockIdx.z;
    const int j0 = jt * JT;

    const float* Xb = X + (size_t)b * Cn * Tn + T0;

    // --- pad rows 60..63 of both X buffers (written once; persist across chunks) ---
    for (int q = tid; q < 4 * 32; q += 256) {
        int c = Cn + (q >> 5), t4 = q & 31;
        *(float4*)((char*)smem + XB0_OFF + (c * XS_STRIDE + t4 * 4) * 4) = make_float4(0.f, 0.f, 0.f, 0.f);
        *(float4*)((char*)smem + XB1_OFF + (c * XS_STRIDE + t4 * 4) * 4) = make_float4(0.f, 0.f, 0.f, 0.f);
    }

    // --- issue chunk 0 and 1 loads ---
    #pragma unroll
    for (int p = 0; p < 2; p++) {
        for (int q = tid; q < Cn * 32; q += 256) {
            int c = q >> 5, t4 = q & 31;
            cp16(xb_u32[p] + (uint32_t)(c * XS_STRIDE + t4 * 4) * 4u,
                 Xb + (size_t)c * Tn + p * 128 + t4 * 4);
        }
        CP_COMMIT();
    }

    // --- w tile -> ws (tf32-rna), zero-padded; overlaps with cp.async flight ---
    for (int q = tid; q < JT * 64; q += 256) {
        int jj = q >> 6, c = q & 63;
        int j = j0 + jj;
        float v = (j < Jn && c < Cn) ? g_w[j * Cn + c] : 0.f;
        ws[jj * WS_STRIDE + c] = tf32_rna(v);
    }

    const uint32_t* wsb = (const uint32_t*)ws;

    #pragma unroll
    for (int p = 0; p < 4; p++) {
        if (p < 3) CP_WAIT(1); else CP_WAIT(0);
        __syncthreads();   // chunk p data + (p==0: ws, pads) visible to all

        const uint32_t* xsb = (const uint32_t*)xbuf[p & 1];
        float acc[3][4][4] = {};

        #pragma unroll
        for (int k0 = 0; k0 < 64; k0 += 8) {
            uint32_t a[3][4];
            #pragma unroll
            for (int mt = 0; mt < 3; mt++) {
                int jm = mw * 48 + mt * 16;
                a[mt][0] = wsb[(jm + gid)     * WS_STRIDE + k0 + tig];
                a[mt][1] = wsb[(jm + gid + 8) * WS_STRIDE + k0 + tig];
                a[mt][2] = wsb[(jm + gid)     * WS_STRIDE + k0 + tig + 4];
                a[mt][3] = wsb[(jm + gid + 8) * WS_STRIDE + k0 + tig + 4];
            }
            uint32_t bv[4][2];
            #pragma unroll
            for (int nt = 0; nt < 4; nt++) {
                int tcol = nw * 32 + nt * 8 + gid;
                bv[nt][0] = xsb[(k0 + tig)     * XS_STRIDE + tcol];
                bv[nt][1] = xsb[(k0 + tig + 4) * XS_STRIDE + tcol];
            }
            #pragma unroll
            for (int mt = 0; mt < 3; mt++)
                #pragma unroll
                for (int nt = 0; nt < 4; nt++)
                    mma8(acc[mt][nt], a[mt], bv[nt]);
        }

        // --- stores for chunk p ---
        #pragma unroll
        for (int mt = 0; mt < 3; mt++) {
            int j = j0 + mw * 48 + mt * 16 + gid;
            #pragma unroll
            for (int nt = 0; nt < 4; nt++) {
                int t = T0 + p * 128 + nw * 32 + nt * 8 + tig * 2;
                float* base = Y + ((size_t)b * Jn + j) * Tn + t;
                if (j < Jn)
                    *(float2*)base = make_float2(acc[mt][nt][0], acc[mt][nt][1]);
                if (j + 8 < Jn)
                    *(float2*)(base + 8 * (size_t)Tn) = make_float2(acc[mt][nt][2], acc[mt][nt][3]);
            }
        }

        __syncthreads();   // all reads of buf[p&1] done before overwrite
        if (p < 2) {
            for (int q = tid; q < Cn * 32; q += 256) {
                int c = q >> 5, t4 = q & 31;
                cp16(xb_u32[p & 1] + (uint32_t)(c * XS_STRIDE + t4 * 4) * 4u,
                     Xb + (size_t)c * Tn + (p + 2) * 128 + t4 * 4);
            }
            CP_COMMIT();
        }
    }
}

// ---------------- launch ----------------
extern "C" void kernel_launch(void* const* d_in, const int* in_sizes, int n_in,
                              void* d_out, int out_size) {
    const float* X = nullptr; const float* z_re = nullptr;
    const float* z_im = nullptr; const float* loc = nullptr;
    for (int i = 0; i < n_in; i++) {
        int s = in_sizes[i];
        if (s == Bn * Cn * Tn)      X = (const float*)d_in[i];
        else if (s == Cn * 2)       loc = (const float*)d_in[i];
        else if (s == Jn * MMn) {
            if (!z_re) z_re = (const float*)d_in[i];
            else       z_im = (const float*)d_in[i];
        }
    }
    float* Y = (float*)d_out;

    (void)cudaFuncSetAttribute(k_main_v4, cudaFuncAttributeMaxDynamicSharedMemorySize, SM_TOTAL);

    k_tables<<<Cn, 256>>>(loc);
    k_logits<<<dim3(9, 2, 8), 256>>>(z_re, z_im);
    k_softmax<<<Jn, 32>>>();
    k_main_v4<<<dim3(3, Tn / 512, Bn), 256, SM_TOTAL>>>(X, Y);
}

// round 12
// speedup vs baseline: 2.1987x; 1.0766x over previous
#include <cuda_runtime.h>
#include <math.h>
#include <stdint.h>

// Problem constants
#define Bn 64
#define Cn 60
#define Tn 4096
#define Jn 270
#define MMn 1024   // K*K = 32*32

// ---------------- device scratch ----------------
__device__ float g_cs[Cn * MMn];         // cos table [c][m]
__device__ float g_sn[Cn * MMn];         // sin table [c][m]
__device__ float g_apart[16 * 288 * 64]; // logit partials [ms][j(288)][c(64)]
__device__ float g_w[Jn * Cn];           // softmax weights [j][c]

__device__ __forceinline__ float tf32_rna(float v) {
    float r; asm("cvt.rna.tf32.f32 %0, %1;" : "=f"(r) : "f"(v)); return r;
}
__device__ __forceinline__ uint32_t smem_u32(const void* p) {
    uint32_t a;
    asm("{ .reg .u64 t; cvta.to.shared.u64 t, %1; cvt.u32.u64 %0, t; }" : "=r"(a) : "l"(p));
    return a;
}
__device__ __forceinline__ void cp16(uint32_t dst, const void* src) {
    asm volatile("cp.async.cg.shared.global [%0], [%1], 16;" :: "r"(dst), "l"(src));
}
#define CP_COMMIT() asm volatile("cp.async.commit_group;" ::: "memory")
#define CP_WAIT(n)  asm volatile("cp.async.wait_group %0;" :: "n"(n) : "memory")

// m16n8k8 tf32 mma: D += A(row,16x8) * B(col,8x8)
__device__ __forceinline__ void mma8(float* d, const uint32_t* a, const uint32_t* b) {
    asm volatile(
        "mma.sync.aligned.m16n8k8.row.col.f32.tf32.tf32.f32 "
        "{%0,%1,%2,%3}, {%4,%5,%6,%7}, {%8,%9}, {%0,%1,%2,%3};"
        : "+f"(d[0]), "+f"(d[1]), "+f"(d[2]), "+f"(d[3])
        : "r"(a[0]), "r"(a[1]), "r"(a[2]), "r"(a[3]), "r"(b[0]), "r"(b[1]));
}

// ---------------- Kernel A: trig tables ----------------
__global__ void k_tables(const float* __restrict__ loc) {
    int c = blockIdx.x;
    float x = loc[c * 2 + 0];
    float y = loc[c * 2 + 1];
    for (int m = threadIdx.x; m < MMn; m += blockDim.x) {
        int k = m >> 5, l = m & 31;
        float r = (float)k * x + (float)l * y;
        r -= rintf(r);
        float s, cv;
        sincospif(2.0f * r, &s, &cv);
        g_cs[c * MMn + m] = cv;
        g_sn[c * MMn + m] = s;
    }
}

// ---------------- Kernel B: logits GEMM (16 m-splits, single 64-m pass) ----------------
__global__ __launch_bounds__(256) void k_logits(const float* __restrict__ z_re,
                                                const float* __restrict__ z_im) {
    __shared__ float zr[32][65], zi[32][65], tc[32][65], ts[32][65];
    int j0 = blockIdx.x * 32;
    int c0 = blockIdx.y * 32;
    int m0 = blockIdx.z * 64;
    int tid = threadIdx.x;
    int tx = tid & 15, ty = tid >> 4;

    for (int i = tid; i < 2048; i += 256) {
        int rr = i >> 6, mm = i & 63;
        int gm = m0 + mm;
        int j = j0 + rr;
        float vr = 0.f, vi = 0.f;
        if (j < Jn) { vr = z_re[j * MMn + gm]; vi = z_im[j * MMn + gm]; }
        zr[rr][mm] = vr; zi[rr][mm] = vi;
        int c = c0 + rr;
        float vc = 0.f, vs = 0.f;
        if (c < Cn) { vc = g_cs[c * MMn + gm]; vs = g_sn[c * MMn + gm]; }
        tc[rr][mm] = vc; ts[rr][mm] = vs;
    }
    __syncthreads();

    float a00 = 0.f, a01 = 0.f, a10 = 0.f, a11 = 0.f;
    #pragma unroll 16
    for (int mm = 0; mm < 64; mm++) {
        float r0 = zr[ty][mm],      r1 = zr[ty + 16][mm];
        float i0 = zi[ty][mm],      i1 = zi[ty + 16][mm];
        float c0v = tc[tx][mm],     c1v = tc[tx + 16][mm];
        float s0v = ts[tx][mm],     s1v = ts[tx + 16][mm];
        a00 += r0 * c0v + i0 * s0v;
        a01 += r0 * c1v + i0 * s1v;
        a10 += r1 * c0v + i1 * s0v;
        a11 += r1 * c1v + i1 * s1v;
    }
    int ms = blockIdx.z;
    g_apart[(ms * 288 + j0 + ty)      * 64 + c0 + tx]      = a00;
    g_apart[(ms * 288 + j0 + ty)      * 64 + c0 + tx + 16] = a01;
    g_apart[(ms * 288 + j0 + ty + 16) * 64 + c0 + tx]      = a10;
    g_apart[(ms * 288 + j0 + ty + 16) * 64 + c0 + tx + 16] = a11;
}

// ---------------- Kernel C: softmax over c per row j ----------------
__global__ void k_softmax() {
    int j = blockIdx.x;
    int lane = threadIdx.x;
    float a1 = 0.f, a2 = 0.f;
    #pragma unroll
    for (int ms = 0; ms < 16; ms++) {
        a1 += g_apart[(ms * 288 + j) * 64 + lane];
        if (lane + 32 < Cn) a2 += g_apart[(ms * 288 + j) * 64 + lane + 32];
    }
    float e1 = expf(a1);
    float e2 = (lane + 32 < Cn) ? expf(a2) : 0.f;
    float s = e1 + e2;
    #pragma unroll
    for (int o = 16; o > 0; o >>= 1) s += __shfl_xor_sync(0xffffffffu, s, o);
    g_w[j * Cn + lane] = e1 / s;
    if (lane + 32 < Cn) g_w[j * Cn + lane + 32] = e2 / s;
}

// ---------------- Kernel D: pipelined mma.sync tf32 GEMM ----------------
// CTA: 96 j x 512 t (4 chunks of 128), double-buffered cp.async X; w loaded once.
// A operand pair-packed: ws2[jj][ks*4+tg] = (w[ks*8+tg], w[ks*8+tg+4]) as float2.
#define JT 96
#define WS2_STRIDE 36   // float2 units per jj row; LDS.64 super-bank = 4*gid+tig, distinct
#define XS_STRIDE 136   // floats; B-frag banks 8*tig+gid -> conflict-free
#define WS_OFF 0u                        // 96*36*8  = 27648 B
#define XB0_OFF 27648u                   // 64*136*4 = 34816 B
#define XB1_OFF (27648u + 34816u)
#define SM_TOTAL (27648u + 2u * 34816u)  // 97280 B -> 2 CTAs/SM

__global__ __launch_bounds__(256, 2) void k_main_v5(const float* __restrict__ X,
                                                    float* __restrict__ Y) {
    extern __shared__ __align__(16) char smem[];
    float2* ws2 = (float2*)(smem + WS_OFF);
    const uint32_t xb_u32[2] = { smem_u32(smem + XB0_OFF), smem_u32(smem + XB1_OFF) };
    const float* xbuf[2] = { (const float*)(smem + XB0_OFF), (const float*)(smem + XB1_OFF) };

    const int tid  = threadIdx.x;
    const int lane = tid & 31;
    const int warp = tid >> 5;
    const int gid  = lane >> 2;    // 0..7
    const int tig  = lane & 3;     // 0..3
    const int mw   = warp & 1;     // j half (48)
    const int nw   = warp >> 1;    // t quarter (32)

    const int jt = blockIdx.x;            // 0..2 fastest -> L2 reuse of X
    const int T0 = blockIdx.y * 512;      // CTA t origin
    const int b  = blockIdx.z;
    const int j0 = jt * JT;

    const float* Xb = X + (size_t)b * Cn * Tn + T0;

    // --- pad rows 60..63 of both X buffers (written once; persist across chunks) ---
    for (int q = tid; q < 4 * 32; q += 256) {
        int c = Cn + (q >> 5), t4 = q & 31;
        *(float4*)((char*)smem + XB0_OFF + (c * XS_STRIDE + t4 * 4) * 4) = make_float4(0.f, 0.f, 0.f, 0.f);
        *(float4*)((char*)smem + XB1_OFF + (c * XS_STRIDE + t4 * 4) * 4) = make_float4(0.f, 0.f, 0.f, 0.f);
    }

    // --- issue chunk 0 and 1 loads ---
    #pragma unroll
    for (int p = 0; p < 2; p++) {
        for (int q = tid; q < Cn * 32; q += 256) {
            int c = q >> 5, t4 = q & 31;
            cp16(xb_u32[p] + (uint32_t)(c * XS_STRIDE + t4 * 4) * 4u,
                 Xb + (size_t)c * Tn + p * 128 + t4 * 4);
        }
        CP_COMMIT();
    }

    // --- w tile -> ws2 (pair-packed, tf32-rna), zero-padded; overlaps cp.async flight ---
    for (int q = tid; q < JT * 32; q += 256) {
        int jj = q >> 5, idx = q & 31;          // idx = ks*4 + tg
        int ks = idx >> 2, tg = idx & 3;
        int k1 = ks * 8 + tg, k2 = k1 + 4;
        int j = j0 + jj;
        float v1 = (j < Jn && k1 < Cn) ? g_w[j * Cn + k1] : 0.f;
        float v2 = (j < Jn && k2 < Cn) ? g_w[j * Cn + k2] : 0.f;
        ws2[jj * WS2_STRIDE + idx] = make_float2(tf32_rna(v1), tf32_rna(v2));
    }

    const uint2* wsb2 = (const uint2*)ws2;

    #pragma unroll
    for (int p = 0; p < 4; p++) {
        if (p < 3) CP_WAIT(1); else CP_WAIT(0);
        __syncthreads();   // chunk p data + (p==0: ws2, pads) visible to all

        const uint32_t* xsb = (const uint32_t*)xbuf[p & 1];
        float acc[3][4][4] = {};

        #pragma unroll
        for (int ks = 0; ks < 8; ks++) {
            uint32_t a[3][4];
            #pragma unroll
            for (int mt = 0; mt < 3; mt++) {
                int jm = mw * 48 + mt * 16;
                uint2 pA = wsb2[(jm + gid)     * WS2_STRIDE + ks * 4 + tig];
                uint2 pB = wsb2[(jm + gid + 8) * WS2_STRIDE + ks * 4 + tig];
                a[mt][0] = pA.x; a[mt][2] = pA.y;
                a[mt][1] = pB.x; a[mt][3] = pB.y;
            }
            uint32_t bv[4][2];
            #pragma unroll
            for (int nt = 0; nt < 4; nt++) {
                int tcol = nw * 32 + nt * 8 + gid;
                bv[nt][0] = xsb[(ks * 8 + tig)     * XS_STRIDE + tcol];
                bv[nt][1] = xsb[(ks * 8 + tig + 4) * XS_STRIDE + tcol];
            }
            #pragma unroll
            for (int mt = 0; mt < 3; mt++)
                #pragma unroll
                for (int nt = 0; nt < 4; nt++)
                    mma8(acc[mt][nt], a[mt], bv[nt]);
        }

        // release buffer and issue next load BEFORE the stores
        if (p < 2) {
            __syncthreads();   // all warps done reading buf[p&1]
            for (int q = tid; q < Cn * 32; q += 256) {
                int c = q >> 5, t4 = q & 31;
                cp16(xb_u32[p & 1] + (uint32_t)(c * XS_STRIDE + t4 * 4) * 4u,
                     Xb + (size_t)c * Tn + (p + 2) * 128 + t4 * 4);
            }
            CP_COMMIT();
        }

        // --- stores for chunk p ---
        #pragma unroll
        for (int mt = 0; mt < 3; mt++) {
            int j = j0 + mw * 48 + mt * 16 + gid;
            #pragma unroll
            for (int nt = 0; nt < 4; nt++) {
                int t = T0 + p * 128 + nw * 32 + nt * 8 + tig * 2;
                float* base = Y + ((size_t)b * Jn + j) * Tn + t;
                if (j < Jn)
                    *(float2*)base = make_float2(acc[mt][nt][0], acc[mt][nt][1]);
                if (j + 8 < Jn)
                    *(float2*)(base + 8 * (size_t)Tn) = make_float2(acc[mt][nt][2], acc[mt][nt][3]);
            }
        }
    }
}

// ---------------- launch ----------------
extern "C" void kernel_launch(void* const* d_in, const int* in_sizes, int n_in,
                              void* d_out, int out_size) {
    const float* X = nullptr; const float* z_re = nullptr;
    const float* z_im = nullptr; const float* loc = nullptr;
    for (int i = 0; i < n_in; i++) {
        int s = in_sizes[i];
        if (s == Bn * Cn * Tn)      X = (const float*)d_in[i];
        else if (s == Cn * 2)       loc = (const float*)d_in[i];
        else if (s == Jn * MMn) {
            if (!z_re) z_re = (const float*)d_in[i];
            else       z_im = (const float*)d_in[i];
        }
    }
    float* Y = (float*)d_out;

    (void)cudaFuncSetAttribute(k_main_v5, cudaFuncAttributeMaxDynamicSharedMemorySize, SM_TOTAL);

    k_tables<<<Cn, 256>>>(loc);
    k_logits<<<dim3(9, 2, 16), 256>>>(z_re, z_im);
    k_softmax<<<Jn, 32>>>();
    k_main_v5<<<dim3(3, Tn / 512, Bn), 256, SM_TOTAL>>>(X, Y);
}